// round 14
// baseline (speedup 1.0000x reference)
#include <cuda_runtime.h>
#include <cuda_fp16.h>
#include <math.h>

#define NUM_INITS 64
#define PSTRIDE   46922
#define OFF_WDENSE 832
#define OFF_BDENSE 46912

// Dense weights pre-swizzled into fp16 B-fragment order:
// [init][wg(2)][w(144)][lane(32)] -> uint4 {b0_nt0, b1_nt0, b0_nt1, b1_nt1}
__device__ uint4 g_wdh[128 * 144 * 32];   // 9.4 MB

__device__ __forceinline__ unsigned pack_h2(float lo, float hi) {
    __half2 h = __floats2half2_rn(lo, hi);
    return *(unsigned*)&h;
}

#define MMA_F16(c0,c1,c2,c3,a0,a1,a2,a3,b0,b1) \
    asm("mma.sync.aligned.m16n8k16.row.col.f32.f16.f16.f32 " \
        "{%0,%1,%2,%3}, {%4,%5,%6,%7}, {%8,%9}, {%0,%1,%2,%3};" \
        : "+f"(c0), "+f"(c1), "+f"(c2), "+f"(c3) \
        : "r"(a0), "r"(a1), "r"(a2), "r"(a3), "r"(b0), "r"(b1))

// ============================================================================
// Prep: swizzle dense weights -> fp16 B fragments, COALESCED reads.
// grid 128 = (init, wg), 256 threads; warp = fragment role, lanes sweep w.
// ============================================================================
__global__ void __launch_bounds__(256)
prep_wd_kernel(const float* __restrict__ params)
{
    const int blk    = blockIdx.x;        // init*2 + wg
    const int init   = blk >> 1;
    const int wg     = blk & 1;
    const int warpid = threadIdx.x >> 5;
    const int lane   = threadIdx.x & 31;
    const float* __restrict__ W = params + (size_t)init * PSTRIDE + OFF_WDENSE;

    #pragma unroll 1
    for (int role = warpid; role < 32; role += 8) {
        int g   = role >> 2;
        int tb  = role & 3;
        int ch0 = wg * 16 + 2 * tb;
        #pragma unroll 1
        for (int w0 = 0; w0 < 144; w0 += 32) {
            int w = w0 + lane;
            if (w < 144) {
                #define WD(o, ch) W[(size_t)(o) * 4608 + (ch) * 144 + w]
                unsigned b0n0 = pack_h2(WD(g, ch0),     WD(g, ch0 + 1));
                unsigned b1n0 = pack_h2(WD(g, ch0 + 8), WD(g, ch0 + 9));
                unsigned b0n1 = 0, b1n1 = 0;
                if (g + 8 < 10) {
                    b0n1 = pack_h2(WD(g + 8, ch0),     WD(g + 8, ch0 + 1));
                    b1n1 = pack_h2(WD(g + 8, ch0 + 8), WD(g + 8, ch0 + 9));
                }
                #undef WD
                g_wdh[(size_t)(blk * 144 + w) * 32 + role] =
                    make_uint4(b0n0, b1n0, b0n1, b1n1);
            }
        }
    }
}

// ============================================================================
// Fused: conv5x5 (fp16 mma, 32 ch/warp) + pool + bias + relu + dense + softmax
// grid 512 = (init, img-tile of 16), 192 threads = 6 warps -> 4 blocks/SM,
// whole grid resident in ONE wave (592 capacity >= 512 blocks).
// warp owns pool-rows {2*warp, 2*warp+1}; j sweeps its 24 windows.
// ============================================================================
#define IMG_H   792
#define IMG_W   396
#define K1_THREADS 192
#define K1_SMEM (2 * 16 * IMG_H * 2)       // 50688 B

__global__ void __launch_bounds__(K1_THREADS, 4)
fused_kernel(const float* __restrict__ params,
             const float* __restrict__ batch,
             float* __restrict__ out)
{
    extern __shared__ __align__(16) unsigned s_mem[];
    __half*   pA  = (__half*)s_mem;                 // [16][792]
    __half*   pB  = (__half*)s_mem + 16 * IMG_H;    // [16][792], pixel c at c+1
    unsigned* pAu = (unsigned*)pA;
    unsigned* pBu = (unsigned*)pB;

    const int blk  = blockIdx.x;
    const int init = blk >> 3;
    const int n0   = (blk & 7) * 16;
    const int t    = threadIdx.x;
    const int warp = t >> 5;      // 0..5 -> pool rows 2*warp, 2*warp+1
    const int lane = t & 31;
    const int g    = lane >> 2;   // 0..7
    const int tid  = lane & 3;    // 0..3

    const float* __restrict__ P = params + (size_t)init * PSTRIDE;

    // ---- stage 16 images into two fp16 planes ----
    for (int u = t; u < 16 * 196; u += K1_THREADS) {
        int im = u / 196, q = u - im * 196;
        float4 v = ((const float4*)(batch + (size_t)(n0 + im) * 784))[q];
        pAu[im * IMG_W + 2 * q    ] = pack_h2(v.x, v.y);
        pAu[im * IMG_W + 2 * q + 1] = pack_h2(v.z, v.w);
        __half* pb = pB + im * IMG_H + 4 * q + 1;
        pb[0] = __float2half(v.x); pb[1] = __float2half(v.y);
        pb[2] = __float2half(v.z); pb[3] = __float2half(v.w);
    }
    for (int v = t; v < 128; v += K1_THREADS) {
        int im = v >> 3, r = v & 7;
        pA[im * IMG_H + 784 + r] = __float2half(0.f);
        pB[im * IMG_H + (r == 0 ? 0 : 784 + r)] = __float2half(0.f);
    }
    __syncthreads();

    // ---- k-slot permutation ----
    const int pky[2][8] = {{0,0,1,1,2,2,3,3},{4,4,0,1,2,3,4,0}};
    const int pkx[2][8] = {{0,2,0,2,0,2,0,2},{0,2,4,4,4,4,4,0}};
    int kwlo[2], kwhi[2];
    #pragma unroll
    for (int s = 0; s < 2; ++s) {
        kwlo[s] = pky[s][tid]     * 14 + (pkx[s][tid]     >> 1);
        kwhi[s] = pky[s][tid + 4] * 14 + (pkx[s][tid + 4] >> 1);
    }

    // ---- conv B fragments: ALL 32 channels (4 ntiles) ----
    unsigned bfr[4][2][2];
    #pragma unroll
    for (int nt = 0; nt < 4; ++nt) {
        int base = (nt * 8 + g) * 25;
        #pragma unroll
        for (int s = 0; s < 2; ++s) {
            {
                int ky = pky[s][tid], kx = pkx[s][tid];
                float wl = P[base + ky * 5 + kx];
                float wh = (kx < 4) ? P[base + ky * 5 + kx + 1] : 0.f;
                bfr[nt][s][0] = pack_h2(wl, wh);
            }
            {
                int q = tid + 4;
                int ky = pky[s][q], kx = pkx[s][q];
                bool dum = (s == 1 && q == 7);
                float wl = dum ? 0.f : P[base + ky * 5 + kx];
                float wh = (!dum && kx < 4) ? P[base + ky * 5 + kx + 1] : 0.f;
                bfr[nt][s][1] = pack_h2(wl, wh);
            }
        }
    }
    float cbias[4][2];
    #pragma unroll
    for (int nt = 0; nt < 4; ++nt)
        #pragma unroll
        for (int jj = 0; jj < 2; ++jj)
            cbias[nt][jj] = P[800 + nt * 8 + 2 * tid + jj];

    const uint4* __restrict__ wd0 =
        g_wdh + (size_t)((init * 2    ) * 144) * 32 + lane;
    const uint4* __restrict__ wd1 =
        g_wdh + (size_t)((init * 2 + 1) * 144) * 32 + lane;

    float dc[2][4];
    #pragma unroll
    for (int q = 0; q < 4; ++q) { dc[0][q] = 0.f; dc[1][q] = 0.f; }

    // ---- main loop: this warp's 24 windows (rows 2*warp..2*warp+1) ----
    #pragma unroll 1
    for (int j = 0; j < 24; ++j) {
        int wy = 2 * warp + (j >= 12);
        int wx = (j >= 12) ? (j - 12) : j;
        int w  = wy * 12 + wx;
        uint4 Bv0 = wd0[(size_t)w * 32];   // dense B, ch 0-15
        uint4 Bv1 = wd1[(size_t)w * 32];   // dense B, ch 16-31

        float pc[4][4];
        #pragma unroll
        for (int p = 0; p < 4; ++p) {
            int dy = p >> 1, dx = p & 1;
            int rowoff = (2 * wy + dy) * 14 + wx + dx;
            const unsigned* __restrict__ pl = dx ? pBu : pAu;
            int b0 = g * IMG_W + rowoff;
            int b1 = b0 + 8 * IMG_W;

            unsigned a[2][4];
            #pragma unroll
            for (int s = 0; s < 2; ++s) {
                a[s][0] = pl[b0 + kwlo[s]];
                a[s][1] = pl[b1 + kwlo[s]];
                a[s][2] = pl[b0 + kwhi[s]];
                a[s][3] = pl[b1 + kwhi[s]];
            }
            #pragma unroll
            for (int nt = 0; nt < 4; ++nt) {
                float c0 = 0.f, c1 = 0.f, c2 = 0.f, c3 = 0.f;
                MMA_F16(c0, c1, c2, c3,
                        a[0][0], a[0][1], a[0][2], a[0][3],
                        bfr[nt][0][0], bfr[nt][0][1]);
                MMA_F16(c0, c1, c2, c3,
                        a[1][0], a[1][1], a[1][2], a[1][3],
                        bfr[nt][1][0], bfr[nt][1][1]);
                if (p == 0) {
                    pc[nt][0] = c0; pc[nt][1] = c1;
                    pc[nt][2] = c2; pc[nt][3] = c3;
                } else {
                    pc[nt][0] = fmaxf(pc[nt][0], c0);
                    pc[nt][1] = fmaxf(pc[nt][1], c1);
                    pc[nt][2] = fmaxf(pc[nt][2], c2);
                    pc[nt][3] = fmaxf(pc[nt][3], c3);
                }
            }
        }

        // bias + relu
        #pragma unroll
        for (int nt = 0; nt < 4; ++nt) {
            pc[nt][0] = fmaxf(pc[nt][0] + cbias[nt][0], 0.f);
            pc[nt][1] = fmaxf(pc[nt][1] + cbias[nt][1], 0.f);
            pc[nt][2] = fmaxf(pc[nt][2] + cbias[nt][0], 0.f);
            pc[nt][3] = fmaxf(pc[nt][3] + cbias[nt][1], 0.f);
        }

        // dense: A = 16img x 32ch, two k-steps of 16
        unsigned a0 = pack_h2(pc[0][0], pc[0][1]);
        unsigned a1 = pack_h2(pc[0][2], pc[0][3]);
        unsigned a2 = pack_h2(pc[1][0], pc[1][1]);
        unsigned a3 = pack_h2(pc[1][2], pc[1][3]);
        unsigned a4 = pack_h2(pc[2][0], pc[2][1]);
        unsigned a5 = pack_h2(pc[2][2], pc[2][3]);
        unsigned a6 = pack_h2(pc[3][0], pc[3][1]);
        unsigned a7 = pack_h2(pc[3][2], pc[3][3]);

        MMA_F16(dc[0][0], dc[0][1], dc[0][2], dc[0][3],
                a0, a1, a2, a3, Bv0.x, Bv0.y);
        MMA_F16(dc[1][0], dc[1][1], dc[1][2], dc[1][3],
                a0, a1, a2, a3, Bv0.z, Bv0.w);
        MMA_F16(dc[0][0], dc[0][1], dc[0][2], dc[0][3],
                a4, a5, a6, a7, Bv1.x, Bv1.y);
        MMA_F16(dc[1][0], dc[1][1], dc[1][2], dc[1][3],
                a4, a5, a6, a7, Bv1.z, Bv1.w);
    }

    // ---- reduce 6 warps' partial dense C, bias, log_softmax ----
    __syncthreads();
    float* s_red = (float*)s_mem;           // [6][16 img][16 out]
    float* s_log = (float*)s_mem + 6 * 256;
    {
        float* wr = s_red + warp * 256;
        wr[ g      * 16 + 2 * tid    ] = dc[0][0];
        wr[ g      * 16 + 2 * tid + 1] = dc[0][1];
        wr[(g + 8) * 16 + 2 * tid    ] = dc[0][2];
        wr[(g + 8) * 16 + 2 * tid + 1] = dc[0][3];
        wr[ g      * 16 + 8 + 2 * tid    ] = dc[1][0];
        wr[ g      * 16 + 8 + 2 * tid + 1] = dc[1][1];
        wr[(g + 8) * 16 + 8 + 2 * tid    ] = dc[1][2];
        wr[(g + 8) * 16 + 8 + 2 * tid + 1] = dc[1][3];
    }
    __syncthreads();

    if (t < 160) {
        int img = t / 10, o = t % 10;
        float s = 0.f;
        #pragma unroll
        for (int wp = 0; wp < 6; ++wp) s += s_red[wp * 256 + img * 16 + o];
        s_log[t] = s + P[OFF_BDENSE + o];
    }
    __syncthreads();

    if (t < 16) {
        float v[10], m = -1e30f;
        #pragma unroll
        for (int o = 0; o < 10; ++o) { v[o] = s_log[t * 10 + o]; m = fmaxf(m, v[o]); }
        float su = 0.f;
        #pragma unroll
        for (int o = 0; o < 10; ++o) su += expf(v[o] - m);
        float ls = m + logf(su);
        float* op = out + ((size_t)init * 128 + n0 + t) * 10;
        #pragma unroll
        for (int o = 0; o < 10; ++o) op[o] = v[o] - ls;
    }
}

// ============================================================================
extern "C" void kernel_launch(void* const* d_in, const int* in_sizes, int n_in,
                              void* d_out, int out_size)
{
    const float* params = (const float*)d_in[0];   // [64, 46922]
    const float* batch  = (const float*)d_in[1];   // [128, 1, 28, 28]
    float* out          = (float*)d_out;           // [64, 128, 10]

    cudaFuncSetAttribute(fused_kernel,
                         cudaFuncAttributeMaxDynamicSharedMemorySize, K1_SMEM);

    prep_wd_kernel<<<128, 256>>>(params);
    fused_kernel<<<512, K1_THREADS, K1_SMEM>>>(params, batch, out);
}

// round 15
// speedup vs baseline: 1.1905x; 1.1905x over previous
#include <cuda_runtime.h>
#include <cuda_fp16.h>
#include <math.h>

#define NUM_INITS 64
#define PSTRIDE   46922
#define OFF_WDENSE 832
#define OFF_BDENSE 46912

// Dense weights pre-swizzled into fp16 B-fragment order:
// [init][wg(2)][w(144)][lane(32)] -> uint4 {b0_nt0, b1_nt0, b0_nt1, b1_nt1}
__device__ uint4 g_wdh[128 * 144 * 32];   // 9.4 MB

__device__ __forceinline__ unsigned pack_h2(float lo, float hi) {
    __half2 h = __floats2half2_rn(lo, hi);
    return *(unsigned*)&h;
}
__device__ __forceinline__ unsigned hmax2u(unsigned a, unsigned b) {
    __half2 r = __hmax2(*(__half2*)&a, *(__half2*)&b);
    return *(unsigned*)&r;
}
__device__ __forceinline__ unsigned hadd2u(unsigned a, unsigned b) {
    __half2 r = __hadd2(*(__half2*)&a, *(__half2*)&b);
    return *(unsigned*)&r;
}

// fp32-accumulate fp16 MMA (dense)
#define MMA_F16(c0,c1,c2,c3,a0,a1,a2,a3,b0,b1) \
    asm("mma.sync.aligned.m16n8k16.row.col.f32.f16.f16.f32 " \
        "{%0,%1,%2,%3}, {%4,%5,%6,%7}, {%8,%9}, {%0,%1,%2,%3};" \
        : "+f"(c0), "+f"(c1), "+f"(c2), "+f"(c3) \
        : "r"(a0), "r"(a1), "r"(a2), "r"(a3), "r"(b0), "r"(b1))

// fp16-accumulate fp16 MMA (conv): D/C are 2 x .f16x2 regs
#define MMA_F16C(d0,d1,a0,a1,a2,a3,b0,b1) \
    asm("mma.sync.aligned.m16n8k16.row.col.f16.f16.f16.f16 " \
        "{%0,%1}, {%2,%3,%4,%5}, {%6,%7}, {%0,%1};" \
        : "+r"(d0), "+r"(d1) \
        : "r"(a0), "r"(a1), "r"(a2), "r"(a3), "r"(b0), "r"(b1))

// ============================================================================
// Prep: swizzle dense weights -> fp16 B fragments, coalesced, 512 blocks.
// blk = init*8 + wg*4 + rq ; block handles 8 roles x 144 w.
// ============================================================================
__global__ void __launch_bounds__(256)
prep_wd_kernel(const float* __restrict__ params)
{
    const int blk    = blockIdx.x;        // 0..511
    const int init   = blk >> 3;
    const int wg     = (blk >> 2) & 1;
    const int rq     = blk & 3;           // role quarter
    const int warpid = threadIdx.x >> 5;
    const int lane   = threadIdx.x & 31;
    const float* __restrict__ W = params + (size_t)init * PSTRIDE + OFF_WDENSE;
    const int obase  = (init * 2 + wg) * 144;

    const int role = rq * 8 + warpid;     // 0..31
    {
        int g   = role >> 2;
        int tb  = role & 3;
        int ch0 = wg * 16 + 2 * tb;
        #pragma unroll 1
        for (int w0 = 0; w0 < 144; w0 += 32) {
            int w = w0 + lane;
            if (w < 144) {
                #define WD(o, ch) W[(size_t)(o) * 4608 + (ch) * 144 + w]
                unsigned b0n0 = pack_h2(WD(g, ch0),     WD(g, ch0 + 1));
                unsigned b1n0 = pack_h2(WD(g, ch0 + 8), WD(g, ch0 + 9));
                unsigned b0n1 = 0, b1n1 = 0;
                if (g + 8 < 10) {
                    b0n1 = pack_h2(WD(g + 8, ch0),     WD(g + 8, ch0 + 1));
                    b1n1 = pack_h2(WD(g + 8, ch0 + 8), WD(g + 8, ch0 + 9));
                }
                #undef WD
                g_wdh[(size_t)(obase + w) * 32 + role] =
                    make_uint4(b0n0, b1n0, b0n1, b1n1);
            }
        }
    }
}

// ============================================================================
// Fused: conv5x5 (fp16 mma, fp16 accum) + pool + bias + relu + dense + softmax
// grid 512 = (init, img-tile of 16), 512 threads = 16 warps,
// <=64 regs -> 2 blocks/SM = 32 warps/SM. warp owns 9 windows.
// ============================================================================
#define IMG_H   792
#define IMG_W   396
#define K1_THREADS 512
#define K1_SMEM (2 * 16 * IMG_H * 2)       // 50688 B

__global__ void __launch_bounds__(K1_THREADS, 2)
fused_kernel(const float* __restrict__ params,
             const float* __restrict__ batch,
             float* __restrict__ out)
{
    extern __shared__ __align__(16) unsigned s_mem[];
    __half*   pA  = (__half*)s_mem;                 // [16][792]
    __half*   pB  = (__half*)s_mem + 16 * IMG_H;    // [16][792], pixel c at c+1
    unsigned* pAu = (unsigned*)pA;
    unsigned* pBu = (unsigned*)pB;

    const int blk  = blockIdx.x;
    const int init = blk >> 3;
    const int n0   = (blk & 7) * 16;
    const int t    = threadIdx.x;
    const int warp = t >> 5;      // 0..15 -> windows warp*9 .. warp*9+8
    const int lane = t & 31;
    const int g    = lane >> 2;   // 0..7
    const int tid  = lane & 3;    // 0..3

    const float* __restrict__ P = params + (size_t)init * PSTRIDE;

    // ---- stage 16 images into two fp16 planes ----
    for (int u = t; u < 16 * 196; u += K1_THREADS) {
        int im = u / 196, q = u - im * 196;
        float4 v = ((const float4*)(batch + (size_t)(n0 + im) * 784))[q];
        pAu[im * IMG_W + 2 * q    ] = pack_h2(v.x, v.y);
        pAu[im * IMG_W + 2 * q + 1] = pack_h2(v.z, v.w);
        __half* pb = pB + im * IMG_H + 4 * q + 1;
        pb[0] = __float2half(v.x); pb[1] = __float2half(v.y);
        pb[2] = __float2half(v.z); pb[3] = __float2half(v.w);
    }
    for (int v = t; v < 128; v += K1_THREADS) {
        int im = v >> 3, r = v & 7;
        pA[im * IMG_H + 784 + r] = __float2half(0.f);
        pB[im * IMG_H + (r == 0 ? 0 : 784 + r)] = __float2half(0.f);
    }
    __syncthreads();

    // ---- k-slot permutation ----
    const int pky[2][8] = {{0,0,1,1,2,2,3,3},{4,4,0,1,2,3,4,0}};
    const int pkx[2][8] = {{0,2,0,2,0,2,0,2},{0,2,4,4,4,4,4,0}};
    int kwlo[2], kwhi[2];
    #pragma unroll
    for (int s = 0; s < 2; ++s) {
        kwlo[s] = pky[s][tid]     * 14 + (pkx[s][tid]     >> 1);
        kwhi[s] = pky[s][tid + 4] * 14 + (pkx[s][tid + 4] >> 1);
    }

    // ---- conv B fragments: ALL 32 channels (4 ntiles) ----
    unsigned bfr[4][2][2];
    #pragma unroll
    for (int nt = 0; nt < 4; ++nt) {
        int base = (nt * 8 + g) * 25;
        #pragma unroll
        for (int s = 0; s < 2; ++s) {
            {
                int ky = pky[s][tid], kx = pkx[s][tid];
                float wl = P[base + ky * 5 + kx];
                float wh = (kx < 4) ? P[base + ky * 5 + kx + 1] : 0.f;
                bfr[nt][s][0] = pack_h2(wl, wh);
            }
            {
                int q = tid + 4;
                int ky = pky[s][q], kx = pkx[s][q];
                bool dum = (s == 1 && q == 7);
                float wl = dum ? 0.f : P[base + ky * 5 + kx];
                float wh = (!dum && kx < 4) ? P[base + ky * 5 + kx + 1] : 0.f;
                bfr[nt][s][1] = pack_h2(wl, wh);
            }
        }
    }
    // conv bias as half2 (fp16 path)
    unsigned cbias[4];
    #pragma unroll
    for (int nt = 0; nt < 4; ++nt)
        cbias[nt] = pack_h2(P[800 + nt * 8 + 2 * tid],
                            P[800 + nt * 8 + 2 * tid + 1]);

    const uint4* __restrict__ wd =
        g_wdh + (size_t)((init * 2) * 144) * 32 + lane;

    float dc[2][4];
    #pragma unroll
    for (int q = 0; q < 4; ++q) { dc[0][q] = 0.f; dc[1][q] = 0.f; }

    // ---- main loop: this warp's 9 windows ----
    int wy = (warp * 9) / 12;
    int wx = (warp * 9) - wy * 12;
    #pragma unroll 1
    for (int j = 0; j < 9; ++j) {
        int w = wy * 12 + wx;
        uint4 Bv0 = wd[(size_t)w * 32];             // dense B, ch 0-15
        uint4 Bv1 = wd[(size_t)(144 + w) * 32];     // dense B, ch 16-31

        unsigned pcm[4][2];   // pooled conv accum, half2 {ch 2tid, 2tid+1}
        #pragma unroll
        for (int p = 0; p < 4; ++p) {
            int dy = p >> 1, dx = p & 1;
            int rowoff = (2 * wy + dy) * 14 + wx + dx;
            const unsigned* __restrict__ pl = dx ? pBu : pAu;
            int b0 = g * IMG_W + rowoff;
            int b1 = b0 + 8 * IMG_W;

            unsigned a[2][4];
            #pragma unroll
            for (int s = 0; s < 2; ++s) {
                a[s][0] = pl[b0 + kwlo[s]];
                a[s][1] = pl[b1 + kwlo[s]];
                a[s][2] = pl[b0 + kwhi[s]];
                a[s][3] = pl[b1 + kwhi[s]];
            }
            #pragma unroll
            for (int nt = 0; nt < 4; ++nt) {
                unsigned d0 = 0u, d1 = 0u;
                MMA_F16C(d0, d1,
                         a[0][0], a[0][1], a[0][2], a[0][3],
                         bfr[nt][0][0], bfr[nt][0][1]);
                MMA_F16C(d0, d1,
                         a[1][0], a[1][1], a[1][2], a[1][3],
                         bfr[nt][1][0], bfr[nt][1][1]);
                if (p == 0) {
                    pcm[nt][0] = d0; pcm[nt][1] = d1;
                } else {
                    pcm[nt][0] = hmax2u(pcm[nt][0], d0);
                    pcm[nt][1] = hmax2u(pcm[nt][1], d1);
                }
            }
        }

        // bias + relu in half2; pcm regs ARE the dense A fragments
        #pragma unroll
        for (int nt = 0; nt < 4; ++nt) {
            pcm[nt][0] = hmax2u(hadd2u(pcm[nt][0], cbias[nt]), 0u);
            pcm[nt][1] = hmax2u(hadd2u(pcm[nt][1], cbias[nt]), 0u);
        }

        MMA_F16(dc[0][0], dc[0][1], dc[0][2], dc[0][3],
                pcm[0][0], pcm[0][1], pcm[1][0], pcm[1][1], Bv0.x, Bv0.y);
        MMA_F16(dc[1][0], dc[1][1], dc[1][2], dc[1][3],
                pcm[0][0], pcm[0][1], pcm[1][0], pcm[1][1], Bv0.z, Bv0.w);
        MMA_F16(dc[0][0], dc[0][1], dc[0][2], dc[0][3],
                pcm[2][0], pcm[2][1], pcm[3][0], pcm[3][1], Bv1.x, Bv1.y);
        MMA_F16(dc[1][0], dc[1][1], dc[1][2], dc[1][3],
                pcm[2][0], pcm[2][1], pcm[3][0], pcm[3][1], Bv1.z, Bv1.w);

        if (++wx == 12) { wx = 0; ++wy; }
    }

    // ---- reduce 16 warps' partial dense C, bias, log_softmax ----
    __syncthreads();
    float* s_red = (float*)s_mem;           // [16][16 img][16 out]
    float* s_log = (float*)s_mem + 16 * 256;
    {
        float* wr = s_red + warp * 256;
        wr[ g      * 16 + 2 * tid    ] = dc[0][0];
        wr[ g      * 16 + 2 * tid + 1] = dc[0][1];
        wr[(g + 8) * 16 + 2 * tid    ] = dc[0][2];
        wr[(g + 8) * 16 + 2 * tid + 1] = dc[0][3];
        wr[ g      * 16 + 8 + 2 * tid    ] = dc[1][0];
        wr[ g      * 16 + 8 + 2 * tid + 1] = dc[1][1];
        wr[(g + 8) * 16 + 8 + 2 * tid    ] = dc[1][2];
        wr[(g + 8) * 16 + 8 + 2 * tid + 1] = dc[1][3];
    }
    __syncthreads();

    if (t < 160) {
        int img = t / 10, o = t % 10;
        float s = 0.f;
        #pragma unroll
        for (int wp = 0; wp < 16; ++wp) s += s_red[wp * 256 + img * 16 + o];
        s_log[t] = s + P[OFF_BDENSE + o];
    }
    __syncthreads();

    if (t < 16) {
        float v[10], m = -1e30f;
        #pragma unroll
        for (int o = 0; o < 10; ++o) { v[o] = s_log[t * 10 + o]; m = fmaxf(m, v[o]); }
        float su = 0.f;
        #pragma unroll
        for (int o = 0; o < 10; ++o) su += expf(v[o] - m);
        float ls = m + logf(su);
        float* op = out + ((size_t)init * 128 + n0 + t) * 10;
        #pragma unroll
        for (int o = 0; o < 10; ++o) op[o] = v[o] - ls;
    }
}

// ============================================================================
extern "C" void kernel_launch(void* const* d_in, const int* in_sizes, int n_in,
                              void* d_out, int out_size)
{
    const float* params = (const float*)d_in[0];   // [64, 46922]
    const float* batch  = (const float*)d_in[1];   // [128, 1, 28, 28]
    float* out          = (float*)d_out;           // [64, 128, 10]

    cudaFuncSetAttribute(fused_kernel,
                         cudaFuncAttributeMaxDynamicSharedMemorySize, K1_SMEM);

    prep_wd_kernel<<<512, 256>>>(params);
    fused_kernel<<<512, K1_THREADS, K1_SMEM>>>(params, batch, out);
}

// round 16
// speedup vs baseline: 1.2533x; 1.0527x over previous
#include <cuda_runtime.h>
#include <cuda_fp16.h>
#include <math.h>

#define NUM_INITS 64
#define PSTRIDE   46922
#define OFF_WDENSE 832
#define OFF_BDENSE 46912

// Dense weights pre-swizzled into fp16 B-fragment order:
// [init][wg(2)][w(144)][lane(32)] -> uint4 {b0_nt0, b1_nt0, b0_nt1, b1_nt1}
__device__ uint4 g_wdh[128 * 144 * 32];   // 9.4 MB

__device__ __forceinline__ unsigned pack_h2(float lo, float hi) {
    __half2 h = __floats2half2_rn(lo, hi);
    return *(unsigned*)&h;
}
__device__ __forceinline__ unsigned hmax2u(unsigned a, unsigned b) {
    __half2 r = __hmax2(*(__half2*)&a, *(__half2*)&b);
    return *(unsigned*)&r;
}

// fp32-accumulate fp16 MMA (dense)
#define MMA_F16(c0,c1,c2,c3,a0,a1,a2,a3,b0,b1) \
    asm("mma.sync.aligned.m16n8k16.row.col.f32.f16.f16.f32 " \
        "{%0,%1,%2,%3}, {%4,%5,%6,%7}, {%8,%9}, {%0,%1,%2,%3};" \
        : "+f"(c0), "+f"(c1), "+f"(c2), "+f"(c3) \
        : "r"(a0), "r"(a1), "r"(a2), "r"(a3), "r"(b0), "r"(b1))

// fp16-accumulate fp16 MMA, C operand separate (bias init)
#define MMA_F16C3(d0,d1,a0,a1,a2,a3,b0,b1,cc) \
    asm("mma.sync.aligned.m16n8k16.row.col.f16.f16.f16.f16 " \
        "{%0,%1}, {%2,%3,%4,%5}, {%6,%7}, {%8,%8};" \
        : "=r"(d0), "=r"(d1) \
        : "r"(a0), "r"(a1), "r"(a2), "r"(a3), "r"(b0), "r"(b1), "r"(cc))

// fp16-accumulate fp16 MMA, accumulate into D
#define MMA_F16A(d0,d1,a0,a1,a2,a3,b0,b1) \
    asm("mma.sync.aligned.m16n8k16.row.col.f16.f16.f16.f16 " \
        "{%0,%1}, {%2,%3,%4,%5}, {%6,%7}, {%0,%1};" \
        : "+r"(d0), "+r"(d1) \
        : "r"(a0), "r"(a1), "r"(a2), "r"(a3), "r"(b0), "r"(b1))

// shared load with literal immediate offset
#define LDSW(v, a, IMM) \
    asm volatile("ld.shared.b32 %0, [%1+%2];" : "=r"(v) : "r"(a), "n"(IMM))

// ============================================================================
// Prep: swizzle dense weights -> fp16 B fragments, coalesced, 512 blocks.
// ============================================================================
__global__ void __launch_bounds__(256)
prep_wd_kernel(const float* __restrict__ params)
{
    const int blk    = blockIdx.x;        // 0..511
    const int init   = blk >> 3;
    const int wg     = (blk >> 2) & 1;
    const int rq     = blk & 3;
    const int warpid = threadIdx.x >> 5;
    const int lane   = threadIdx.x & 31;
    const float* __restrict__ W = params + (size_t)init * PSTRIDE + OFF_WDENSE;
    const int obase  = (init * 2 + wg) * 144;

    const int role = rq * 8 + warpid;     // 0..31
    {
        int g   = role >> 2;
        int tb  = role & 3;
        int ch0 = wg * 16 + 2 * tb;
        #pragma unroll 1
        for (int w0 = 0; w0 < 144; w0 += 32) {
            int w = w0 + lane;
            if (w < 144) {
                #define WD(o, ch) W[(size_t)(o) * 4608 + (ch) * 144 + w]
                unsigned b0n0 = pack_h2(WD(g, ch0),     WD(g, ch0 + 1));
                unsigned b1n0 = pack_h2(WD(g, ch0 + 8), WD(g, ch0 + 9));
                unsigned b0n1 = 0, b1n1 = 0;
                if (g + 8 < 10) {
                    b0n1 = pack_h2(WD(g + 8, ch0),     WD(g + 8, ch0 + 1));
                    b1n1 = pack_h2(WD(g + 8, ch0 + 8), WD(g + 8, ch0 + 9));
                }
                #undef WD
                g_wdh[(size_t)(obase + w) * 32 + role] =
                    make_uint4(b0n0, b1n0, b0n1, b1n1);
            }
        }
    }
}

// ============================================================================
// Fused kernel. grid 512 = (init, img-tile of 16), 512 threads = 16 warps,
// 64 regs -> 2 blocks/SM = 32 warps/SM. warp owns 9 consecutive windows.
// Conv LDS via running smem address regs + literal immediates.
// Position immediates (bytes): dy*56 + dx*(25344+4); +12672 for img row g+8.
// ============================================================================
#define IMG_H   792
#define IMG_W   396
#define K1_THREADS 512
#define K1_SMEM (2 * 16 * IMG_H * 2)       // 50688 B

// 8 loads + 8 MMAs for one conv position; FIRST selects init-vs-max pooling
#define DO_POS(IMM, FIRST) { \
    unsigned x0,x1,x2,x3,y0,y1,y2,y3; \
    LDSW(x0, ad0, (IMM));         LDSW(x1, ad0, (IMM)+12672); \
    LDSW(x2, ad1, (IMM));         LDSW(x3, ad1, (IMM)+12672); \
    LDSW(y0, ad2, (IMM));         LDSW(y1, ad2, (IMM)+12672); \
    LDSW(y2, ad3, (IMM));         LDSW(y3, ad3, (IMM)+12672); \
    _Pragma("unroll") \
    for (int nt = 0; nt < 4; ++nt) { \
        unsigned d0, d1; \
        MMA_F16C3(d0, d1, x0, x1, x2, x3, \
                  bfr[nt][0][0], bfr[nt][0][1], cbias[nt]); \
        MMA_F16A(d0, d1, y0, y1, y2, y3, \
                 bfr[nt][1][0], bfr[nt][1][1]); \
        if (FIRST) { pcm[nt][0] = d0; pcm[nt][1] = d1; } \
        else { pcm[nt][0] = hmax2u(pcm[nt][0], d0); \
               pcm[nt][1] = hmax2u(pcm[nt][1], d1); } \
    } }

__global__ void __launch_bounds__(K1_THREADS, 2)
fused_kernel(const float* __restrict__ params,
             const float* __restrict__ batch,
             float* __restrict__ out)
{
    extern __shared__ __align__(16) unsigned s_mem[];
    __half*   pA  = (__half*)s_mem;                 // [16][792]
    __half*   pB  = (__half*)s_mem + 16 * IMG_H;    // [16][792], pixel c at c+1
    unsigned* pAu = (unsigned*)pA;

    const int blk  = blockIdx.x;
    const int init = blk >> 3;
    const int n0   = (blk & 7) * 16;
    const int t    = threadIdx.x;
    const int warp = t >> 5;      // 0..15 -> windows warp*9 .. warp*9+8
    const int lane = t & 31;
    const int g    = lane >> 2;   // 0..7
    const int tid  = lane & 3;    // 0..3

    const float* __restrict__ P = params + (size_t)init * PSTRIDE;

    // ---- stage 16 images into two fp16 planes ----
    for (int u = t; u < 16 * 196; u += K1_THREADS) {
        int im = u / 196, q = u - im * 196;
        float4 v = ((const float4*)(batch + (size_t)(n0 + im) * 784))[q];
        pAu[im * IMG_W + 2 * q    ] = pack_h2(v.x, v.y);
        pAu[im * IMG_W + 2 * q + 1] = pack_h2(v.z, v.w);
        __half* pb = pB + im * IMG_H + 4 * q + 1;
        pb[0] = __float2half(v.x); pb[1] = __float2half(v.y);
        pb[2] = __float2half(v.z); pb[3] = __float2half(v.w);
    }
    for (int v = t; v < 128; v += K1_THREADS) {
        int im = v >> 3, r = v & 7;
        pA[im * IMG_H + 784 + r] = __float2half(0.f);
        pB[im * IMG_H + (r == 0 ? 0 : 784 + r)] = __float2half(0.f);
    }
    __syncthreads();

    // ---- k-slot permutation ----
    const int pky[2][8] = {{0,0,1,1,2,2,3,3},{4,4,0,1,2,3,4,0}};
    const int pkx[2][8] = {{0,2,0,2,0,2,0,2},{0,2,4,4,4,4,4,0}};
    int kwlo[2], kwhi[2];
    #pragma unroll
    for (int s = 0; s < 2; ++s) {
        kwlo[s] = pky[s][tid]     * 14 + (pkx[s][tid]     >> 1);
        kwhi[s] = pky[s][tid + 4] * 14 + (pkx[s][tid + 4] >> 1);
    }

    // ---- conv B fragments: ALL 32 channels (4 ntiles) ----
    unsigned bfr[4][2][2];
    #pragma unroll
    for (int nt = 0; nt < 4; ++nt) {
        int base = (nt * 8 + g) * 25;
        #pragma unroll
        for (int s = 0; s < 2; ++s) {
            {
                int ky = pky[s][tid], kx = pkx[s][tid];
                float wl = P[base + ky * 5 + kx];
                float wh = (kx < 4) ? P[base + ky * 5 + kx + 1] : 0.f;
                bfr[nt][s][0] = pack_h2(wl, wh);
            }
            {
                int q = tid + 4;
                int ky = pky[s][q], kx = pkx[s][q];
                bool dum = (s == 1 && q == 7);
                float wl = dum ? 0.f : P[base + ky * 5 + kx];
                float wh = (!dum && kx < 4) ? P[base + ky * 5 + kx + 1] : 0.f;
                bfr[nt][s][1] = pack_h2(wl, wh);
            }
        }
    }
    // conv bias as half2 (used as MMA C operand)
    unsigned cbias[4];
    #pragma unroll
    for (int nt = 0; nt < 4; ++nt)
        cbias[nt] = pack_h2(P[800 + nt * 8 + 2 * tid],
                            P[800 + nt * 8 + 2 * tid + 1]);

    const uint4* __restrict__ wd =
        g_wdh + (size_t)((init * 2) * 144) * 32 + lane;

    float dc[2][4];
    #pragma unroll
    for (int q = 0; q < 4; ++q) { dc[0][q] = 0.f; dc[1][q] = 0.f; }

    // ---- running smem addresses for conv A loads ----
    int wy = (warp * 9) / 12;
    int wx = (warp * 9) - wy * 12;
    unsigned sbase = (unsigned)__cvta_generic_to_shared(s_mem);
    unsigned r0    = sbase + 4u * (g * IMG_W + 2 * wy * 14 + wx);
    unsigned ad0 = r0 + 4u * kwlo[0];
    unsigned ad1 = r0 + 4u * kwhi[0];
    unsigned ad2 = r0 + 4u * kwlo[1];
    unsigned ad3 = r0 + 4u * kwhi[1];

    // ---- main loop: this warp's 9 windows ----
    int w = warp * 9;
    #pragma unroll 1
    for (int j = 0; j < 9; ++j) {
        uint4 Bv0 = wd[(size_t)w * 32];             // dense B, ch 0-15
        uint4 Bv1 = wd[(size_t)(144 + w) * 32];     // dense B, ch 16-31

        unsigned pcm[4][2];   // pooled conv accum (+bias), half2
        DO_POS(0,     true);      // dy=0 dx=0
        DO_POS(25348, false);     // dy=0 dx=1 (plane B, +1 word)
        DO_POS(56,    false);     // dy=1 dx=0
        DO_POS(25404, false);     // dy=1 dx=1

        // relu (bias already in accum via C operand)
        #pragma unroll
        for (int nt = 0; nt < 4; ++nt) {
            pcm[nt][0] = hmax2u(pcm[nt][0], 0u);
            pcm[nt][1] = hmax2u(pcm[nt][1], 0u);
        }

        MMA_F16(dc[0][0], dc[0][1], dc[0][2], dc[0][3],
                pcm[0][0], pcm[0][1], pcm[1][0], pcm[1][1], Bv0.x, Bv0.y);
        MMA_F16(dc[1][0], dc[1][1], dc[1][2], dc[1][3],
                pcm[0][0], pcm[0][1], pcm[1][0], pcm[1][1], Bv0.z, Bv0.w);
        MMA_F16(dc[0][0], dc[0][1], dc[0][2], dc[0][3],
                pcm[2][0], pcm[2][1], pcm[3][0], pcm[3][1], Bv1.x, Bv1.y);
        MMA_F16(dc[1][0], dc[1][1], dc[1][2], dc[1][3],
                pcm[2][0], pcm[2][1], pcm[3][0], pcm[3][1], Bv1.z, Bv1.w);

        ++w;
        if (++wx == 12) {          // row wrap: +17 words
            wx = 0; ++wy;
            ad0 += 68; ad1 += 68; ad2 += 68; ad3 += 68;
        } else {                   // next column: +1 word
            ad0 += 4; ad1 += 4; ad2 += 4; ad3 += 4;
        }
    }

    // ---- reduce 16 warps' partial dense C, bias, log_softmax ----
    __syncthreads();
    float* s_red = (float*)s_mem;           // [16][16 img][16 out]
    float* s_log = (float*)s_mem + 16 * 256;
    {
        float* wr = s_red + warp * 256;
        wr[ g      * 16 + 2 * tid    ] = dc[0][0];
        wr[ g      * 16 + 2 * tid + 1] = dc[0][1];
        wr[(g + 8) * 16 + 2 * tid    ] = dc[0][2];
        wr[(g + 8) * 16 + 2 * tid + 1] = dc[0][3];
        wr[ g      * 16 + 8 + 2 * tid    ] = dc[1][0];
        wr[ g      * 16 + 8 + 2 * tid + 1] = dc[1][1];
        wr[(g + 8) * 16 + 8 + 2 * tid    ] = dc[1][2];
        wr[(g + 8) * 16 + 8 + 2 * tid + 1] = dc[1][3];
    }
    __syncthreads();

    if (t < 160) {
        int img = t / 10, o = t % 10;
        float s = 0.f;
        #pragma unroll
        for (int wp = 0; wp < 16; ++wp) s += s_red[wp * 256 + img * 16 + o];
        s_log[t] = s + P[OFF_BDENSE + o];
    }
    __syncthreads();

    if (t < 16) {
        float v[10], m = -1e30f;
        #pragma unroll
        for (int o = 0; o < 10; ++o) { v[o] = s_log[t * 10 + o]; m = fmaxf(m, v[o]); }
        float su = 0.f;
        #pragma unroll
        for (int o = 0; o < 10; ++o) su += expf(v[o] - m);
        float ls = m + logf(su);
        float* op = out + ((size_t)init * 128 + n0 + t) * 10;
        #pragma unroll
        for (int o = 0; o < 10; ++o) op[o] = v[o] - ls;
    }
}

// ============================================================================
extern "C" void kernel_launch(void* const* d_in, const int* in_sizes, int n_in,
                              void* d_out, int out_size)
{
    const float* params = (const float*)d_in[0];   // [64, 46922]
    const float* batch  = (const float*)d_in[1];   // [128, 1, 28, 28]
    float* out          = (float*)d_out;           // [64, 128, 10]

    cudaFuncSetAttribute(fused_kernel,
                         cudaFuncAttributeMaxDynamicSharedMemorySize, K1_SMEM);

    prep_wd_kernel<<<512, 256>>>(params);
    fused_kernel<<<512, K1_THREADS, K1_SMEM>>>(params, batch, out);
}